// round 1
// baseline (speedup 1.0000x reference)
#include <cuda_runtime.h>

#define NN      10000
#define NE      160000
#define NR      4
#define NG      256
#define F3      712
#define MAXD    1024

// ---------------- static device scratch (no allocations allowed) ----------------
__device__ float g_AX[(size_t)NN * 5 * MAXD];   // stacked GEMM A operand [N, 5*D]
__device__ float g_h1[(size_t)NN * 1024];       // layer1 out; reused for layer3 out
__device__ float g_h2[(size_t)NN * 1024];       // layer2 out
__device__ float g_inv[NN * NR];                // per (dst, rel) 1/count
__device__ float g_pool[NG * F3];
__device__ float g_pcnt[NG];

// ---------------- counts ----------------
__global__ void k_zero_inv() {
    int i = blockIdx.x * blockDim.x + threadIdx.x;
    if (i < NN * NR) g_inv[i] = 0.f;
}

__global__ void k_count(const int* __restrict__ dst, const int* __restrict__ et) {
    int i = blockIdx.x * blockDim.x + threadIdx.x;
    if (i < NE) atomicAdd(&g_inv[dst[i] * NR + et[i]], 1.f);
}

__global__ void k_inv() {
    int i = blockIdx.x * blockDim.x + threadIdx.x;
    if (i < NN * NR) g_inv[i] = 1.f / fmaxf(g_inv[i], 1.f);
}

// ---------------- build stacked A operand: zero agg region + copy x into root slot ----------------
// AX row layout (floats): [0, 4D) relation aggregates (zeroed here), [4D, 5D) = input row
__global__ void k_prep(const float* __restrict__ x0, int sel, int D) {
    int rowlen4 = 5 * D / 4;          // float4 per AX row
    long total = (long)NN * rowlen4;
    long i = (long)blockIdx.x * blockDim.x + threadIdx.x;
    if (i >= total) return;
    int n = (int)(i / rowlen4);
    int j = (int)(i % rowlen4);
    const float* src = (sel == 0) ? x0 : (sel == 1 ? g_h1 : g_h2);
    float4 v = make_float4(0.f, 0.f, 0.f, 0.f);
    if (j >= D) {                      // 4D floats == D float4s of zero region
        v = ((const float4*)src)[(long)n * (D / 4) + (j - D)];
    }
    ((float4*)g_AX)[i] = v;
}

// ---------------- edge aggregation: AX[dst, r*D + d] += x[src, d] * inv[dst, r] ----------------
__global__ void k_agg(const float* __restrict__ x0, int sel,
                      const int* __restrict__ src, const int* __restrict__ dst,
                      const int* __restrict__ et, int D) {
    int per = D / 4;                   // float4 per node row
    long total = (long)NE * per;
    long i = (long)blockIdx.x * blockDim.x + threadIdx.x;
    if (i >= total) return;
    int e = (int)(i / per);
    int j = (int)(i % per);
    const float* x = (sel == 0) ? x0 : (sel == 1 ? g_h1 : g_h2);
    int s  = src[e];
    int dd = dst[e];
    int t  = et[e];
    float sc = g_inv[dd * NR + t];
    float4 v = ((const float4*)x)[(long)s * per + j];
    float* base = g_AX + (long)dd * 5 * D + t * D + j * 4;
    atomicAdd(base + 0, v.x * sc);
    atomicAdd(base + 1, v.y * sc);
    atomicAdd(base + 2, v.z * sc);
    atomicAdd(base + 3, v.w * sc);
}

// ---------------- fused stacked GEMM + bias + relu ----------------
// out[n,f] = relu( sum_k AX[n,k] * B[k,f] + bias[f] ),  B row k: k<Kw -> W[k], else root[k-Kw]
__global__ __launch_bounds__(256, 2)
void k_gemm(const float* __restrict__ W, const float* __restrict__ root,
            const float* __restrict__ bias,
            int M, int K, int Kw, int F, int osel) {
    __shared__ float As[16][128];
    __shared__ float Bs[16][128];

    const float* A = g_AX;
    float* out = (osel == 1) ? g_h1 : g_h2;

    int t = threadIdx.x;
    int row0 = blockIdx.y * 128;
    int col0 = blockIdx.x * 128;
    int tm = (t >> 4) << 3;            // 0..120, step 8
    int tn = (t & 15) << 3;            // 0..120, step 8

    float acc[8][8];
#pragma unroll
    for (int i = 0; i < 8; i++)
#pragma unroll
        for (int j = 0; j < 8; j++) acc[i][j] = 0.f;

    for (int kt = 0; kt < K; kt += 16) {
        // A tile: 128 rows x 16 k, transposed into As[k][m]
#pragma unroll
        for (int l = 0; l < 2; l++) {
            int id = t + l * 256;      // 0..511
            int m  = id >> 2;
            int kq = id & 3;
            float4 v = make_float4(0.f, 0.f, 0.f, 0.f);
            int row = row0 + m;
            if (row < M) v = *(const float4*)(A + (long)row * K + kt + kq * 4);
            As[kq * 4 + 0][m] = v.x;
            As[kq * 4 + 1][m] = v.y;
            As[kq * 4 + 2][m] = v.z;
            As[kq * 4 + 3][m] = v.w;
        }
        // B tile: 16 k rows x 128 cols
#pragma unroll
        for (int l = 0; l < 2; l++) {
            int id = t + l * 256;
            int kb = id >> 5;
            int c4 = id & 31;
            int col = col0 + c4 * 4;
            int krow = kt + kb;
            float4 v = make_float4(0.f, 0.f, 0.f, 0.f);
            if (col < F) {
                const float* bp = (krow < Kw) ? (W + (long)krow * F)
                                              : (root + (long)(krow - Kw) * F);
                v = *(const float4*)(bp + col);
            }
            *(float4*)&Bs[kb][c4 * 4] = v;
        }
        __syncthreads();

#pragma unroll
        for (int kk = 0; kk < 16; kk++) {
            float a[8], b[8];
            *(float4*)(a)     = *(float4*)&As[kk][tm];
            *(float4*)(a + 4) = *(float4*)&As[kk][tm + 4];
            *(float4*)(b)     = *(float4*)&Bs[kk][tn];
            *(float4*)(b + 4) = *(float4*)&Bs[kk][tn + 4];
#pragma unroll
            for (int i = 0; i < 8; i++)
#pragma unroll
                for (int j = 0; j < 8; j++) acc[i][j] += a[i] * b[j];
        }
        __syncthreads();
    }

    // epilogue: bias + relu
#pragma unroll
    for (int i = 0; i < 8; i++) {
        int row = row0 + tm + i;
        if (row < M) {
#pragma unroll
            for (int j = 0; j < 8; j += 4) {
                int col = col0 + tn + j;
                if (col < F) {
                    float4 v;
                    v.x = fmaxf(acc[i][j + 0] + bias[col + 0], 0.f);
                    v.y = fmaxf(acc[i][j + 1] + bias[col + 1], 0.f);
                    v.z = fmaxf(acc[i][j + 2] + bias[col + 2], 0.f);
                    v.w = fmaxf(acc[i][j + 3] + bias[col + 3], 0.f);
                    *(float4*)(out + (long)row * F + col) = v;
                }
            }
        }
    }
}

// ---------------- pooling ----------------
__global__ void k_zero_pool() {
    int i = blockIdx.x * blockDim.x + threadIdx.x;
    if (i < NG * F3) g_pool[i] = 0.f;
    if (i < NG) g_pcnt[i] = 0.f;
}

__global__ void k_pcnt(const int* __restrict__ batch) {
    int i = blockIdx.x * blockDim.x + threadIdx.x;
    if (i < NN) atomicAdd(&g_pcnt[batch[i]], 1.f);
}

__global__ void k_pool(const int* __restrict__ batch) {
    const int per = F3 / 4;            // 178
    long total = (long)NN * per;
    long i = (long)blockIdx.x * blockDim.x + threadIdx.x;
    if (i >= total) return;
    int n = (int)(i / per);
    int j = (int)(i % per);
    int b = batch[n];
    float4 v = ((const float4*)g_h1)[(long)n * per + j];   // h3 lives in g_h1
    float* base = g_pool + (long)b * F3 + j * 4;
    atomicAdd(base + 0, v.x);
    atomicAdd(base + 1, v.y);
    atomicAdd(base + 2, v.z);
    atomicAdd(base + 3, v.w);
}

// ---------------- final MLP: [G,712] -> relu fc(64) -> fc(1) ----------------
__global__ void k_mlp(const float* __restrict__ fw1, const float* __restrict__ fb1,
                      const float* __restrict__ fw2, const float* __restrict__ fb2,
                      float* __restrict__ out) {
    __shared__ float gbuf[F3];
    __shared__ float abuf[64];
    int g = blockIdx.x;
    int t = threadIdx.x;
    float invc = 1.f / fmaxf(g_pcnt[g], 1.f);
    for (int i = t; i < F3; i += blockDim.x)
        gbuf[i] = g_pool[(long)g * F3 + i] * invc;
    __syncthreads();
    if (t < 64) {
        float s = fb1[t];
        for (int k = 0; k < F3; k++) s += gbuf[k] * fw1[k * 64 + t];
        abuf[t] = fmaxf(s, 0.f);
    }
    __syncthreads();
    if (t == 0) {
        float o = fb2[0];
#pragma unroll
        for (int j = 0; j < 64; j++) o += abuf[j] * fw2[j];
        out[g] = o;
    }
}

// ---------------- launch ----------------
extern "C" void kernel_launch(void* const* d_in, const int* in_sizes, int n_in,
                              void* d_out, int out_size) {
    const float* x    = (const float*)d_in[0];
    const int*   ei   = (const int*)d_in[1];
    const int*   et   = (const int*)d_in[2];
    const int*   batch= (const int*)d_in[3];
    const float* W1   = (const float*)d_in[4];
    const float* r1   = (const float*)d_in[5];
    const float* b1   = (const float*)d_in[6];
    const float* W2   = (const float*)d_in[7];
    const float* r2   = (const float*)d_in[8];
    const float* b2   = (const float*)d_in[9];
    const float* W3   = (const float*)d_in[10];
    const float* r3   = (const float*)d_in[11];
    const float* b3   = (const float*)d_in[12];
    const float* fw1  = (const float*)d_in[13];
    const float* fb1  = (const float*)d_in[14];
    const float* fw2  = (const float*)d_in[15];
    const float* fb2  = (const float*)d_in[16];
    float* out = (float*)d_out;

    const int* srcI = ei;
    const int* dstI = ei + NE;

    // per-(dst, rel) inverse counts (graph-constant, but recomputed for determinism)
    k_zero_inv<<<(NN * NR + 255) / 256, 256>>>();
    k_count<<<(NE + 255) / 256, 256>>>(dstI, et);
    k_inv<<<(NN * NR + 255) / 256, 256>>>();

    // ---- layer 1: D=64 -> F=1024, out g_h1 (osel=1), src sel=0 (x) ----
    {
        const int D = 64, F = 1024, K = 5 * D;
        long t4 = (long)NN * 5 * D / 4;
        k_prep<<<(int)((t4 + 255) / 256), 256>>>(x, 0, D);
        long ta = (long)NE * D / 4;
        k_agg<<<(int)((ta + 255) / 256), 256>>>(x, 0, srcI, dstI, et, D);
        dim3 grid((F + 127) / 128, (NN + 127) / 128);
        k_gemm<<<grid, 256>>>(W1, r1, b1, NN, K, 4 * D, F, 1);
    }
    // ---- layer 2: D=1024 -> F=1024, in g_h1 (sel=1), out g_h2 (osel=2) ----
    {
        const int D = 1024, F = 1024, K = 5 * D;
        long t4 = (long)NN * 5 * D / 4;
        k_prep<<<(int)((t4 + 255) / 256), 256>>>(x, 1, D);
        long ta = (long)NE * D / 4;
        k_agg<<<(int)((ta + 255) / 256), 256>>>(x, 1, srcI, dstI, et, D);
        dim3 grid((F + 127) / 128, (NN + 127) / 128);
        k_gemm<<<grid, 256>>>(W2, r2, b2, NN, K, 4 * D, F, 2);
    }
    // ---- layer 3: D=1024 -> F=712, in g_h2 (sel=2), out g_h1 (osel=1) ----
    {
        const int D = 1024, F = F3, K = 5 * D;
        long t4 = (long)NN * 5 * D / 4;
        k_prep<<<(int)((t4 + 255) / 256), 256>>>(x, 2, D);
        long ta = (long)NE * D / 4;
        k_agg<<<(int)((ta + 255) / 256), 256>>>(x, 2, srcI, dstI, et, D);
        dim3 grid((F + 127) / 128, (NN + 127) / 128);
        k_gemm<<<grid, 256>>>(W3, r3, b3, NN, K, 4 * D, F, 1);
    }

    // ---- global mean pool + MLP ----
    k_zero_pool<<<(NG * F3 + 255) / 256, 256>>>();
    k_pcnt<<<(NN + 255) / 256, 256>>>(batch);
    {
        long tp = (long)NN * (F3 / 4);
        k_pool<<<(int)((tp + 255) / 256), 256>>>(batch);
    }
    k_mlp<<<NG, 128>>>(fw1, fb1, fw2, fb2, out);
}

// round 5
// speedup vs baseline: 1.7548x; 1.7548x over previous
#include <cuda_runtime.h>

#define NN      10000
#define NE      160000
#define NR      4
#define NG      256
#define F3      712
#define MAXD    1024

// ---------------- static device scratch (no allocations allowed) ----------------
__device__ float g_AX[(size_t)NN * 5 * MAXD];   // stacked GEMM A operand [N, 5*D]
__device__ float g_h1[(size_t)NN * 1024];       // layer1 out; reused for layer3 out
__device__ float g_h2[(size_t)NN * 1024];       // layer2 out
__device__ float g_inv[NN * NR];                // per (dst, rel) 1/count
__device__ float g_pool[NG * F3];
__device__ float g_pcnt[NG];

// ---------------- counts ----------------
__global__ void k_zero_inv() {
    int i = blockIdx.x * blockDim.x + threadIdx.x;
    if (i < NN * NR) g_inv[i] = 0.f;
}
__global__ void k_count(const int* __restrict__ dst, const int* __restrict__ et) {
    int i = blockIdx.x * blockDim.x + threadIdx.x;
    if (i < NE) atomicAdd(&g_inv[dst[i] * NR + et[i]], 1.f);
}
__global__ void k_inv() {
    int i = blockIdx.x * blockDim.x + threadIdx.x;
    if (i < NN * NR) g_inv[i] = 1.f / fmaxf(g_inv[i], 1.f);
}

// ---------------- build stacked A operand ----------------
__global__ void k_prep(const float* __restrict__ x0, int sel, int D) {
    int rowlen4 = 5 * D / 4;
    long total = (long)NN * rowlen4;
    long i = (long)blockIdx.x * blockDim.x + threadIdx.x;
    if (i >= total) return;
    int n = (int)(i / rowlen4);
    int j = (int)(i % rowlen4);
    const float* src = (sel == 0) ? x0 : (sel == 1 ? g_h1 : g_h2);
    float4 v = make_float4(0.f, 0.f, 0.f, 0.f);
    if (j >= D) v = ((const float4*)src)[(long)n * (D / 4) + (j - D)];
    ((float4*)g_AX)[i] = v;
}

// ---------------- edge aggregation ----------------
__global__ void k_agg(const float* __restrict__ x0, int sel,
                      const int* __restrict__ src, const int* __restrict__ dst,
                      const int* __restrict__ et, int D) {
    int per = D / 4;
    long total = (long)NE * per;
    long i = (long)blockIdx.x * blockDim.x + threadIdx.x;
    if (i >= total) return;
    int e = (int)(i / per);
    int j = (int)(i % per);
    const float* x = (sel == 0) ? x0 : (sel == 1 ? g_h1 : g_h2);
    int s  = src[e];
    int dd = dst[e];
    int t  = et[e];
    float sc = g_inv[dd * NR + t];
    float4 v = ((const float4*)x)[(long)s * per + j];
    float* base = g_AX + (long)dd * 5 * D + t * D + j * 4;
    atomicAdd(base + 0, v.x * sc);
    atomicAdd(base + 1, v.y * sc);
    atomicAdd(base + 2, v.z * sc);
    atomicAdd(base + 3, v.w * sc);
}

// ---------------- tf32 mma.sync stacked GEMM (2-term A split, RN) + bias + relu ----
// CTA: 128M x 128N, BK=32, 8 warps of 64x32. A = g_AX [M,K] K-major.
// B row k: k<Kw -> W[k,:], else root[k-Kw,:].  out = relu(A*B + bias)
// Precision: ah = rn_tf32(a), al = rn_tf32(a-ah); b = rn_tf32(b);
//            c += ah*b; c += al*b   (removes truncation bias; ~1e-4 end-to-end)
#define AS_STRIDE 36
#define BS_STRIDE 132
#define ASZ (128 * AS_STRIDE)
#define BSZ (32 * BS_STRIDE)
#define SM_TOTAL_F (2 * ASZ + 2 * BSZ)
#define SM_TOTAL_B (SM_TOTAL_F * 4)  // 70656 bytes

__device__ __forceinline__ void cp_async16(unsigned dst, const float* src, int sz) {
    asm volatile("cp.async.ca.shared.global [%0], [%1], 16, %2;"
                 :: "r"(dst), "l"(src), "r"(sz));
}
__device__ __forceinline__ void cp_commit() {
    asm volatile("cp.async.commit_group;" ::: "memory");
}
__device__ __forceinline__ void cp_wait1() {
    asm volatile("cp.async.wait_group 1;" ::: "memory");
}
__device__ __forceinline__ void cp_wait0() {
    asm volatile("cp.async.wait_group 0;" ::: "memory");
}
__device__ __forceinline__ unsigned rn_tf32(float x) {
    unsigned r;
    asm("cvt.rna.tf32.f32 %0, %1;" : "=r"(r) : "f"(x));
    return r;
}

__global__ __launch_bounds__(256)
void k_gemm_mma(const float* __restrict__ W, const float* __restrict__ root,
                const float* __restrict__ bias, int M, int K, int Kw, int F, int osel) {
    extern __shared__ float sm[];
    const float* A = g_AX;
    float* out = (osel == 1) ? g_h1 : g_h2;

    int t = threadIdx.x, lane = t & 31, wid = t >> 5;
    int row0 = blockIdx.y * 128, col0 = blockIdx.x * 128;
    int m0w = (wid >> 2) * 64, n0w = (wid & 3) * 32;
    int g = lane >> 2, tg = lane & 3;
    int nch = K >> 5;

    float c[4][4][4];
#pragma unroll
    for (int i = 0; i < 4; i++)
#pragma unroll
        for (int j = 0; j < 4; j++)
#pragma unroll
            for (int k = 0; k < 4; k++) c[i][j][k] = 0.f;

    unsigned smb = (unsigned)__cvta_generic_to_shared(sm);

    auto load_chunk = [&](int ch, int buf) {
        unsigned as_b = smb + (buf ? ASZ : 0) * 4;
#pragma unroll
        for (int l = 0; l < 4; l++) {
            int id = t + (l << 8);
            int m = id >> 3, k4 = id & 7;
            int row = row0 + m;
            const float* src = A + (size_t)row * K + (ch << 5) + (k4 << 2);
            cp_async16(as_b + (unsigned)(m * AS_STRIDE + k4 * 4) * 4, src, (row < M) ? 16 : 0);
        }
        unsigned bs_b = smb + (2 * ASZ + (buf ? BSZ : 0)) * 4;
#pragma unroll
        for (int l = 0; l < 4; l++) {
            int id = t + (l << 8);
            int k = id >> 5, n4 = id & 31;
            int krow = (ch << 5) + k;
            int col = col0 + (n4 << 2);
            const float* bp = (krow < Kw) ? (W + (size_t)krow * F + col)
                                          : (root + (size_t)(krow - Kw) * F + col);
            cp_async16(bs_b + (unsigned)(k * BS_STRIDE + n4 * 4) * 4, bp, (col < F) ? 16 : 0);
        }
        cp_commit();
    };

    load_chunk(0, 0);

    for (int ch = 0; ch < nch; ch++) {
        if (ch + 1 < nch) load_chunk(ch + 1, (ch + 1) & 1);
        if (ch + 1 < nch) cp_wait1(); else cp_wait0();
        __syncthreads();

        const float* As = sm + ((ch & 1) ? ASZ : 0);
        const float* Bs = sm + 2 * ASZ + ((ch & 1) ? BSZ : 0);

#pragma unroll
        for (int kk = 0; kk < 32; kk += 8) {
            unsigned b[4][2];
#pragma unroll
            for (int nt = 0; nt < 4; nt++) {
                int n = n0w + nt * 8 + g;
                b[nt][0] = rn_tf32(Bs[(kk + tg) * BS_STRIDE + n]);
                b[nt][1] = rn_tf32(Bs[(kk + 4 + tg) * BS_STRIDE + n]);
            }
#pragma unroll
            for (int mt = 0; mt < 4; mt++) {
                int m = m0w + mt * 16 + g;
                float ar[4];
                ar[0] = As[m * AS_STRIDE + kk + tg];
                ar[1] = As[(m + 8) * AS_STRIDE + kk + tg];
                ar[2] = As[m * AS_STRIDE + kk + 4 + tg];
                ar[3] = As[(m + 8) * AS_STRIDE + kk + 4 + tg];
                unsigned ah[4], al[4];
#pragma unroll
                for (int q = 0; q < 4; q++) {
                    ah[q] = rn_tf32(ar[q]);
                    al[q] = rn_tf32(ar[q] - __uint_as_float(ah[q]));
                }
#pragma unroll
                for (int nt = 0; nt < 4; nt++) {
                    asm volatile(
                        "mma.sync.aligned.m16n8k8.row.col.f32.tf32.tf32.f32 "
                        "{%0,%1,%2,%3},{%4,%5,%6,%7},{%8,%9},{%0,%1,%2,%3};"
                        : "+f"(c[mt][nt][0]), "+f"(c[mt][nt][1]),
                          "+f"(c[mt][nt][2]), "+f"(c[mt][nt][3])
                        : "r"(ah[0]), "r"(ah[1]), "r"(ah[2]), "r"(ah[3]),
                          "r"(b[nt][0]), "r"(b[nt][1]));
                    asm volatile(
                        "mma.sync.aligned.m16n8k8.row.col.f32.tf32.tf32.f32 "
                        "{%0,%1,%2,%3},{%4,%5,%6,%7},{%8,%9},{%0,%1,%2,%3};"
                        : "+f"(c[mt][nt][0]), "+f"(c[mt][nt][1]),
                          "+f"(c[mt][nt][2]), "+f"(c[mt][nt][3])
                        : "r"(al[0]), "r"(al[1]), "r"(al[2]), "r"(al[3]),
                          "r"(b[nt][0]), "r"(b[nt][1]));
                }
            }
        }
        __syncthreads();
    }

    // ---- epilogue: bias + relu ----
#pragma unroll
    for (int mt = 0; mt < 4; mt++) {
        int r0 = row0 + m0w + mt * 16 + g;
#pragma unroll
        for (int nt = 0; nt < 4; nt++) {
            int cb = col0 + n0w + nt * 8 + tg * 2;
            if (cb < F) {
                float b0 = bias[cb], b1 = bias[cb + 1];
                if (r0 < M) {
                    float2 v;
                    v.x = fmaxf(c[mt][nt][0] + b0, 0.f);
                    v.y = fmaxf(c[mt][nt][1] + b1, 0.f);
                    *(float2*)(out + (size_t)r0 * F + cb) = v;
                }
                if (r0 + 8 < M) {
                    float2 v;
                    v.x = fmaxf(c[mt][nt][2] + b0, 0.f);
                    v.y = fmaxf(c[mt][nt][3] + b1, 0.f);
                    *(float2*)(out + (size_t)(r0 + 8) * F + cb) = v;
                }
            }
        }
    }
}

// ---------------- pooling ----------------
__global__ void k_zero_pool() {
    int i = blockIdx.x * blockDim.x + threadIdx.x;
    if (i < NG * F3) g_pool[i] = 0.f;
    if (i < NG) g_pcnt[i] = 0.f;
}
__global__ void k_pcnt(const int* __restrict__ batch) {
    int i = blockIdx.x * blockDim.x + threadIdx.x;
    if (i < NN) atomicAdd(&g_pcnt[batch[i]], 1.f);
}
__global__ void k_pool(const int* __restrict__ batch) {
    const int per = F3 / 4;
    long total = (long)NN * per;
    long i = (long)blockIdx.x * blockDim.x + threadIdx.x;
    if (i >= total) return;
    int n = (int)(i / per);
    int j = (int)(i % per);
    int b = batch[n];
    float4 v = ((const float4*)g_h1)[(long)n * per + j];
    float* base = g_pool + (long)b * F3 + j * 4;
    atomicAdd(base + 0, v.x);
    atomicAdd(base + 1, v.y);
    atomicAdd(base + 2, v.z);
    atomicAdd(base + 3, v.w);
}

// ---------------- final MLP ----------------
__global__ void k_mlp(const float* __restrict__ fw1, const float* __restrict__ fb1,
                      const float* __restrict__ fw2, const float* __restrict__ fb2,
                      float* __restrict__ out) {
    __shared__ float gbuf[F3];
    __shared__ float abuf[64];
    int g = blockIdx.x;
    int t = threadIdx.x;
    float invc = 1.f / fmaxf(g_pcnt[g], 1.f);
    for (int i = t; i < F3; i += blockDim.x)
        gbuf[i] = g_pool[(long)g * F3 + i] * invc;
    __syncthreads();
    if (t < 64) {
        float s = fb1[t];
        for (int k = 0; k < F3; k++) s += gbuf[k] * fw1[k * 64 + t];
        abuf[t] = fmaxf(s, 0.f);
    }
    __syncthreads();
    if (t == 0) {
        float o = fb2[0];
#pragma unroll
        for (int j = 0; j < 64; j++) o += abuf[j] * fw2[j];
        out[g] = o;
    }
}

// ---------------- launch ----------------
extern "C" void kernel_launch(void* const* d_in, const int* in_sizes, int n_in,
                              void* d_out, int out_size) {
    const float* x    = (const float*)d_in[0];
    const int*   ei   = (const int*)d_in[1];
    const int*   et   = (const int*)d_in[2];
    const int*   batch= (const int*)d_in[3];
    const float* W1   = (const float*)d_in[4];
    const float* r1   = (const float*)d_in[5];
    const float* b1   = (const float*)d_in[6];
    const float* W2   = (const float*)d_in[7];
    const float* r2   = (const float*)d_in[8];
    const float* b2   = (const float*)d_in[9];
    const float* W3   = (const float*)d_in[10];
    const float* r3   = (const float*)d_in[11];
    const float* b3   = (const float*)d_in[12];
    const float* fw1  = (const float*)d_in[13];
    const float* fb1  = (const float*)d_in[14];
    const float* fw2  = (const float*)d_in[15];
    const float* fb2  = (const float*)d_in[16];
    float* out = (float*)d_out;

    const int* srcI = ei;
    const int* dstI = ei + NE;

    cudaFuncSetAttribute(k_gemm_mma, cudaFuncAttributeMaxDynamicSharedMemorySize, SM_TOTAL_B);

    k_zero_inv<<<(NN * NR + 255) / 256, 256>>>();
    k_count<<<(NE + 255) / 256, 256>>>(dstI, et);
    k_inv<<<(NN * NR + 255) / 256, 256>>>();

    // ---- layer 1: D=64 -> F=1024 ----
    {
        const int D = 64, F = 1024, K = 5 * D;
        long t4 = (long)NN * 5 * D / 4;
        k_prep<<<(int)((t4 + 255) / 256), 256>>>(x, 0, D);
        long ta = (long)NE * D / 4;
        k_agg<<<(int)((ta + 255) / 256), 256>>>(x, 0, srcI, dstI, et, D);
        dim3 grid((F + 127) / 128, (NN + 127) / 128);
        k_gemm_mma<<<grid, 256, SM_TOTAL_B>>>(W1, r1, b1, NN, K, 4 * D, F, 1);
    }
    // ---- layer 2: D=1024 -> F=1024 ----
    {
        const int D = 1024, F = 1024, K = 5 * D;
        long t4 = (long)NN * 5 * D / 4;
        k_prep<<<(int)((t4 + 255) / 256), 256>>>(x, 1, D);
        long ta = (long)NE * D / 4;
        k_agg<<<(int)((ta + 255) / 256), 256>>>(x, 1, srcI, dstI, et, D);
        dim3 grid((F + 127) / 128, (NN + 127) / 128);
        k_gemm_mma<<<grid, 256, SM_TOTAL_B>>>(W2, r2, b2, NN, K, 4 * D, F, 2);
    }
    // ---- layer 3: D=1024 -> F=712 ----
    {
        const int D = 1024, F = F3, K = 5 * D;
        long t4 = (long)NN * 5 * D / 4;
        k_prep<<<(int)((t4 + 255) / 256), 256>>>(x, 2, D);
        long ta = (long)NE * D / 4;
        k_agg<<<(int)((ta + 255) / 256), 256>>>(x, 2, srcI, dstI, et, D);
        dim3 grid((F + 127) / 128, (NN + 127) / 128);
        k_gemm_mma<<<grid, 256, SM_TOTAL_B>>>(W3, r3, b3, NN, K, 4 * D, F, 1);
    }

    // ---- global mean pool + MLP ----
    k_zero_pool<<<(NG * F3 + 255) / 256, 256>>>();
    k_pcnt<<<(NN + 255) / 256, 256>>>(batch);
    {
        long tp = (long)NN * (F3 / 4);
        k_pool<<<(int)((tp + 255) / 256), 256>>>(batch);
    }
    k_mlp<<<NG, 128>>>(fw1, fb1, fw2, fb2, out);
}

// round 6
// speedup vs baseline: 2.9764x; 1.6961x over previous
#include <cuda_runtime.h>

#define NN      10000
#define NE      160000
#define NR      4
#define NG      256
#define F3      712
#define NBUCK   (NN * NR)
#define NSCANB  ((NBUCK + 255) / 256)

// ---------------- static device scratch (no allocations allowed) ----------------
__device__ float g_AX[(size_t)NN * 4 * 1024];   // aggregated operand [N, 4*D] (D<=1024)
__device__ float g_h1[(size_t)NN * 1024];       // layer1 out; reused for layer3 out
__device__ float g_h2[(size_t)NN * 1024];       // layer2 out
__device__ int   g_cnt[NBUCK];                  // per (dst, rel) edge count
__device__ int   g_off[NBUCK];                  // exclusive offsets (CSR)
__device__ int   g_cur[NBUCK];                  // scatter cursors
__device__ int   g_bsum[NSCANB + 1];            // scan block sums
__device__ int   g_es[NE];                      // src ids sorted by (dst, rel)
__device__ float g_pool[NG * F3];
__device__ float g_pcnt[NG];

// ---------------- CSR build ----------------
__global__ void k_zero_cnt() {
    int i = blockIdx.x * blockDim.x + threadIdx.x;
    if (i < NBUCK) g_cnt[i] = 0;
}
__global__ void k_count(const int* __restrict__ dst, const int* __restrict__ et) {
    int i = blockIdx.x * blockDim.x + threadIdx.x;
    if (i < NE) atomicAdd(&g_cnt[dst[i] * NR + et[i]], 1);
}
// block-wise inclusive scan -> exclusive offsets + block totals
__global__ void k_scanA() {
    __shared__ int sd[256];
    int t = threadIdx.x;
    int i = blockIdx.x * 256 + t;
    int v = (i < NBUCK) ? g_cnt[i] : 0;
    sd[t] = v;
    __syncthreads();
#pragma unroll
    for (int o = 1; o < 256; o <<= 1) {
        int u = (t >= o) ? sd[t - o] : 0;
        __syncthreads();
        sd[t] += u;
        __syncthreads();
    }
    if (i < NBUCK) g_off[i] = sd[t] - v;
    if (t == 255) g_bsum[blockIdx.x] = sd[t];
}
__global__ void k_scanB() {
    if (threadIdx.x == 0) {
        int run = 0;
        for (int b = 0; b < NSCANB; b++) { int s = g_bsum[b]; g_bsum[b] = run; run += s; }
    }
}
__global__ void k_scanC() {
    int i = blockIdx.x * blockDim.x + threadIdx.x;
    if (i < NBUCK) {
        int o = g_off[i] + g_bsum[i >> 8];
        g_off[i] = o;
        g_cur[i] = o;
    }
}
__global__ void k_scatter(const int* __restrict__ src, const int* __restrict__ dst,
                          const int* __restrict__ et) {
    int e = blockIdx.x * blockDim.x + threadIdx.x;
    if (e < NE) {
        int b = dst[e] * NR + et[e];
        int pos = atomicAdd(&g_cur[b], 1);
        g_es[pos] = src[e];
    }
}

// ---------------- CSR aggregation: g_AX[n, r*D + d] = mean over bucket of x[src, d] ----
// blockDim 256; threads-per-node = D/4; writes the whole 4D region (zeros for empty buckets)
__global__ void k_aggcsr(const float* __restrict__ x0, int sel, int D) {
    int per = D >> 2;                   // float4 per row
    int npb = 256 / per;                // nodes per block
    int local = threadIdx.x / per;
    int j = threadIdx.x - local * per;
    int n = blockIdx.x * npb + local;
    if (n >= NN) return;
    const float* x = (sel == 0) ? x0 : (sel == 1 ? g_h1 : g_h2);
    const float4* x4 = (const float4*)x;
    float4* out4 = (float4*)g_AX;
    size_t obase = (size_t)n * (NR * per);
#pragma unroll
    for (int r = 0; r < NR; r++) {
        int b = n * NR + r;
        int start = g_off[b];
        int cnt = g_cnt[b];
        float4 acc = make_float4(0.f, 0.f, 0.f, 0.f);
        for (int e = 0; e < cnt; e++) {
            int s = g_es[start + e];
            float4 v = x4[(size_t)s * per + j];
            acc.x += v.x; acc.y += v.y; acc.z += v.z; acc.w += v.w;
        }
        float inv = 1.f / fmaxf((float)cnt, 1.f);
        acc.x *= inv; acc.y *= inv; acc.z *= inv; acc.w *= inv;
        out4[obase + r * per + j] = acc;
    }
}

// ---------------- tf32 mma.sync stacked GEMM (RN both operands) + bias + relu ----
// CTA: 128M x 128N, BK=32, 8 warps of 64x32.
// Logical A row n = [ g_AX[n, 0..4D) | h[n, 0..D) ], K = 5D, Kw = 4D.
// B row k: k<Kw -> W[k,:], else root[k-Kw,:].  out = relu(A*B + bias)
#define AS_STRIDE 36
#define BS_STRIDE 132
#define ASZ (128 * AS_STRIDE)
#define BSZ (32 * BS_STRIDE)
#define SM_TOTAL_B ((2 * ASZ + 2 * BSZ) * 4)   // 70656 bytes

__device__ __forceinline__ void cp_async16(unsigned dst, const float* src, int sz) {
    asm volatile("cp.async.ca.shared.global [%0], [%1], 16, %2;"
                 :: "r"(dst), "l"(src), "r"(sz));
}
__device__ __forceinline__ void cp_commit() {
    asm volatile("cp.async.commit_group;" ::: "memory");
}
__device__ __forceinline__ void cp_wait1() {
    asm volatile("cp.async.wait_group 1;" ::: "memory");
}
__device__ __forceinline__ void cp_wait0() {
    asm volatile("cp.async.wait_group 0;" ::: "memory");
}
__device__ __forceinline__ unsigned rn_tf32(float x) {
    unsigned r;
    asm("cvt.rna.tf32.f32 %0, %1;" : "=r"(r) : "f"(x));
    return r;
}

__global__ __launch_bounds__(256)
void k_gemm_mma(const float* __restrict__ W, const float* __restrict__ root,
                const float* __restrict__ bias, const float* __restrict__ x0,
                int hsel, int M, int D, int F, int osel) {
    extern __shared__ float sm[];
    const float* H = (hsel == 0) ? x0 : (hsel == 1 ? g_h1 : g_h2);
    float* out = (osel == 1) ? g_h1 : g_h2;
    int K = 5 * D, Kw = 4 * D;

    int t = threadIdx.x, lane = t & 31, wid = t >> 5;
    int row0 = blockIdx.y * 128, col0 = blockIdx.x * 128;
    int m0w = (wid >> 2) * 64, n0w = (wid & 3) * 32;
    int g = lane >> 2, tg = lane & 3;
    int nch = K >> 5;

    float c[4][4][4];
#pragma unroll
    for (int i = 0; i < 4; i++)
#pragma unroll
        for (int j = 0; j < 4; j++)
#pragma unroll
            for (int k = 0; k < 4; k++) c[i][j][k] = 0.f;

    unsigned smb = (unsigned)__cvta_generic_to_shared(sm);

    auto load_chunk = [&](int ch, int buf) {
        unsigned as_b = smb + (buf ? ASZ : 0) * 4;
#pragma unroll
        for (int l = 0; l < 4; l++) {
            int id = t + (l << 8);
            int m = id >> 3, k4 = id & 7;
            int row = row0 + m;
            int krow = (ch << 5) + (k4 << 2);
            const float* src = (krow < Kw) ? (g_AX + (size_t)row * Kw + krow)
                                           : (H + (size_t)row * D + (krow - Kw));
            cp_async16(as_b + (unsigned)(m * AS_STRIDE + k4 * 4) * 4, src, (row < M) ? 16 : 0);
        }
        unsigned bs_b = smb + (2 * ASZ + (buf ? BSZ : 0)) * 4;
#pragma unroll
        for (int l = 0; l < 4; l++) {
            int id = t + (l << 8);
            int k = id >> 5, n4 = id & 31;
            int krow = (ch << 5) + k;
            int col = col0 + (n4 << 2);
            const float* bp = (krow < Kw) ? (W + (size_t)krow * F + col)
                                          : (root + (size_t)(krow - Kw) * F + col);
            cp_async16(bs_b + (unsigned)(k * BS_STRIDE + n4 * 4) * 4, bp, (col < F) ? 16 : 0);
        }
        cp_commit();
    };

    load_chunk(0, 0);

    for (int ch = 0; ch < nch; ch++) {
        if (ch + 1 < nch) load_chunk(ch + 1, (ch + 1) & 1);
        if (ch + 1 < nch) cp_wait1(); else cp_wait0();
        __syncthreads();

        const float* As = sm + ((ch & 1) ? ASZ : 0);
        const float* Bs = sm + 2 * ASZ + ((ch & 1) ? BSZ : 0);

#pragma unroll
        for (int kk = 0; kk < 32; kk += 8) {
            unsigned b[4][2];
#pragma unroll
            for (int nt = 0; nt < 4; nt++) {
                int n = n0w + nt * 8 + g;
                b[nt][0] = rn_tf32(Bs[(kk + tg) * BS_STRIDE + n]);
                b[nt][1] = rn_tf32(Bs[(kk + 4 + tg) * BS_STRIDE + n]);
            }
#pragma unroll
            for (int mt = 0; mt < 4; mt++) {
                int m = m0w + mt * 16 + g;
                unsigned a[4];
                a[0] = rn_tf32(As[m * AS_STRIDE + kk + tg]);
                a[1] = rn_tf32(As[(m + 8) * AS_STRIDE + kk + tg]);
                a[2] = rn_tf32(As[m * AS_STRIDE + kk + 4 + tg]);
                a[3] = rn_tf32(As[(m + 8) * AS_STRIDE + kk + 4 + tg]);
#pragma unroll
                for (int nt = 0; nt < 4; nt++)
                    asm volatile(
                        "mma.sync.aligned.m16n8k8.row.col.f32.tf32.tf32.f32 "
                        "{%0,%1,%2,%3},{%4,%5,%6,%7},{%8,%9},{%0,%1,%2,%3};"
                        : "+f"(c[mt][nt][0]), "+f"(c[mt][nt][1]),
                          "+f"(c[mt][nt][2]), "+f"(c[mt][nt][3])
                        : "r"(a[0]), "r"(a[1]), "r"(a[2]), "r"(a[3]),
                          "r"(b[nt][0]), "r"(b[nt][1]));
            }
        }
        __syncthreads();
    }

    // ---- epilogue: bias + relu ----
#pragma unroll
    for (int mt = 0; mt < 4; mt++) {
        int r0 = row0 + m0w + mt * 16 + g;
#pragma unroll
        for (int nt = 0; nt < 4; nt++) {
            int cb = col0 + n0w + nt * 8 + tg * 2;
            if (cb < F) {
                float b0 = bias[cb], b1 = bias[cb + 1];
                if (r0 < M) {
                    float2 v;
                    v.x = fmaxf(c[mt][nt][0] + b0, 0.f);
                    v.y = fmaxf(c[mt][nt][1] + b1, 0.f);
                    *(float2*)(out + (size_t)r0 * F + cb) = v;
                }
                if (r0 + 8 < M) {
                    float2 v;
                    v.x = fmaxf(c[mt][nt][2] + b0, 0.f);
                    v.y = fmaxf(c[mt][nt][3] + b1, 0.f);
                    *(float2*)(out + (size_t)(r0 + 8) * F + cb) = v;
                }
            }
        }
    }
}

// ---------------- pooling ----------------
__global__ void k_zero_pool() {
    int i = blockIdx.x * blockDim.x + threadIdx.x;
    if (i < NG * F3) g_pool[i] = 0.f;
    if (i < NG) g_pcnt[i] = 0.f;
}
__global__ void k_pcnt(const int* __restrict__ batch) {
    int i = blockIdx.x * blockDim.x + threadIdx.x;
    if (i < NN) atomicAdd(&g_pcnt[batch[i]], 1.f);
}
__global__ void k_pool(const int* __restrict__ batch) {
    const int per = F3 / 4;
    long total = (long)NN * per;
    long i = (long)blockIdx.x * blockDim.x + threadIdx.x;
    if (i >= total) return;
    int n = (int)(i / per);
    int j = (int)(i % per);
    int b = batch[n];
    float4 v = ((const float4*)g_h1)[(long)n * per + j];
    float* base = g_pool + (long)b * F3 + j * 4;
    atomicAdd(base + 0, v.x);
    atomicAdd(base + 1, v.y);
    atomicAdd(base + 2, v.z);
    atomicAdd(base + 3, v.w);
}

// ---------------- final MLP ----------------
__global__ void k_mlp(const float* __restrict__ fw1, const float* __restrict__ fb1,
                      const float* __restrict__ fw2, const float* __restrict__ fb2,
                      float* __restrict__ out) {
    __shared__ float gbuf[F3];
    __shared__ float abuf[64];
    int g = blockIdx.x;
    int t = threadIdx.x;
    float invc = 1.f / fmaxf(g_pcnt[g], 1.f);
    for (int i = t; i < F3; i += blockDim.x)
        gbuf[i] = g_pool[(long)g * F3 + i] * invc;
    __syncthreads();
    if (t < 64) {
        float s = fb1[t];
        for (int k = 0; k < F3; k++) s += gbuf[k] * fw1[k * 64 + t];
        abuf[t] = fmaxf(s, 0.f);
    }
    __syncthreads();
    if (t == 0) {
        float o = fb2[0];
#pragma unroll
        for (int j = 0; j < 64; j++) o += abuf[j] * fw2[j];
        out[g] = o;
    }
}

// ---------------- launch ----------------
extern "C" void kernel_launch(void* const* d_in, const int* in_sizes, int n_in,
                              void* d_out, int out_size) {
    const float* x    = (const float*)d_in[0];
    const int*   ei   = (const int*)d_in[1];
    const int*   et   = (const int*)d_in[2];
    const int*   batch= (const int*)d_in[3];
    const float* W1   = (const float*)d_in[4];
    const float* r1   = (const float*)d_in[5];
    const float* b1   = (const float*)d_in[6];
    const float* W2   = (const float*)d_in[7];
    const float* r2   = (const float*)d_in[8];
    const float* b2   = (const float*)d_in[9];
    const float* W3   = (const float*)d_in[10];
    const float* r3   = (const float*)d_in[11];
    const float* b3   = (const float*)d_in[12];
    const float* fw1  = (const float*)d_in[13];
    const float* fb1  = (const float*)d_in[14];
    const float* fw2  = (const float*)d_in[15];
    const float* fb2  = (const float*)d_in[16];
    float* out = (float*)d_out;

    const int* srcI = ei;
    const int* dstI = ei + NE;

    cudaFuncSetAttribute(k_gemm_mma, cudaFuncAttributeMaxDynamicSharedMemorySize, SM_TOTAL_B);

    // ---- CSR build (graph-constant; recomputed each call for determinism) ----
    k_zero_cnt<<<(NBUCK + 255) / 256, 256>>>();
    k_count<<<(NE + 255) / 256, 256>>>(dstI, et);
    k_scanA<<<NSCANB, 256>>>();
    k_scanB<<<1, 32>>>();
    k_scanC<<<NSCANB, 256>>>();
    k_scatter<<<(NE + 255) / 256, 256>>>(srcI, dstI, et);

    // ---- layer 1: D=64 -> F=1024 ----
    {
        const int D = 64, F = 1024;
        int per = D / 4, npb = 256 / per;
        k_aggcsr<<<(NN + npb - 1) / npb, 256>>>(x, 0, D);
        dim3 grid((F + 127) / 128, (NN + 127) / 128);
        k_gemm_mma<<<grid, 256, SM_TOTAL_B>>>(W1, r1, b1, x, 0, NN, D, F, 1);
    }
    // ---- layer 2: D=1024 -> F=1024 ----
    {
        const int D = 1024, F = 1024;
        k_aggcsr<<<NN, 256>>>(x, 1, D);
        dim3 grid((F + 127) / 128, (NN + 127) / 128);
        k_gemm_mma<<<grid, 256, SM_TOTAL_B>>>(W2, r2, b2, x, 1, NN, D, F, 2);
    }
    // ---- layer 3: D=1024 -> F=712 ----
    {
        const int D = 1024, F = F3;
        k_aggcsr<<<NN, 256>>>(x, 2, D);
        dim3 grid((F + 127) / 128, (NN + 127) / 128);
        k_gemm_mma<<<grid, 256, SM_TOTAL_B>>>(W3, r3, b3, x, 2, NN, D, F, 1);
    }

    // ---- global mean pool + MLP ----
    k_zero_pool<<<(NG * F3 + 255) / 256, 256>>>();
    k_pcnt<<<(NN + 255) / 256, 256>>>(batch);
    {
        long tp = (long)NN * (F3 / 4);
        k_pool<<<(int)((tp + 255) / 256), 256>>>(batch);
    }
    k_mlp<<<NG, 128>>>(fw1, fb1, fw2, fb2, out);
}

// round 7
// speedup vs baseline: 3.9189x; 1.3167x over previous
#include <cuda_runtime.h>

#define NN      10000
#define NE      160000
#define NR      4
#define NG      256
#define F3      712
#define NBUCK   (NN * NR)
#define NSCANB  ((NBUCK + 255) / 256)

// ---------------- static device scratch (no allocations allowed) ----------------
__device__ float g_AX[(size_t)NN * 4 * 1024];   // aggregated operand [N, 4*D], tf32-rounded
__device__ float g_h1[(size_t)NN * 1024];       // layer1 out; reused for layer3 out
__device__ float g_h2[(size_t)NN * 1024];       // layer2 out
__device__ float g_xr[(size_t)NN * 64];         // tf32-rounded input x
__device__ float g_B1[320 * 1024];              // stacked [W1|root1], tf32-rounded
__device__ float g_B2[(size_t)5120 * 1024];     // stacked [W2|root2], tf32-rounded
__device__ float g_B3[(size_t)5120 * 712];      // stacked [W3|root3], tf32-rounded
__device__ int   g_cnt[NBUCK];
__device__ int   g_off[NBUCK];
__device__ int   g_cur[NBUCK];
__device__ int   g_bsum[NSCANB + 1];
__device__ int   g_es[NE];
__device__ float g_pool[NG * F3];
__device__ float g_pcnt[NG];

__device__ __forceinline__ unsigned rn_tf32(float x) {
    unsigned r;
    asm("cvt.rna.tf32.f32 %0, %1;" : "=r"(r) : "f"(x));
    return r;
}
__device__ __forceinline__ float rn_tf32f(float x) {
    return __uint_as_float(rn_tf32(x));
}

// ---------------- weight pre-conversion: dst = rn_tf32([W | root]) ----------------
__global__ void k_wconv(const float* __restrict__ W, const float* __restrict__ root,
                        float* __restrict__ dst, long nW, long nTot) {
    long i = ((long)blockIdx.x * blockDim.x + threadIdx.x) * 4;
    if (i >= nTot) return;
    float4 v = (i < nW) ? *(const float4*)(W + i) : *(const float4*)(root + (i - nW));
    v.x = rn_tf32f(v.x); v.y = rn_tf32f(v.y); v.z = rn_tf32f(v.z); v.w = rn_tf32f(v.w);
    *(float4*)(dst + i) = v;
}
__global__ void k_xconv(const float* __restrict__ x) {
    long i = ((long)blockIdx.x * blockDim.x + threadIdx.x) * 4;
    if (i >= (long)NN * 64) return;
    float4 v = *(const float4*)(x + i);
    v.x = rn_tf32f(v.x); v.y = rn_tf32f(v.y); v.z = rn_tf32f(v.z); v.w = rn_tf32f(v.w);
    *(float4*)(g_xr + i) = v;
}

// ---------------- CSR build ----------------
__global__ void k_zero_cnt() {
    int i = blockIdx.x * blockDim.x + threadIdx.x;
    if (i < NBUCK) g_cnt[i] = 0;
}
__global__ void k_count(const int* __restrict__ dst, const int* __restrict__ et) {
    int i = blockIdx.x * blockDim.x + threadIdx.x;
    if (i < NE) atomicAdd(&g_cnt[dst[i] * NR + et[i]], 1);
}
__global__ void k_scanA() {
    __shared__ int sd[256];
    int t = threadIdx.x;
    int i = blockIdx.x * 256 + t;
    int v = (i < NBUCK) ? g_cnt[i] : 0;
    sd[t] = v;
    __syncthreads();
#pragma unroll
    for (int o = 1; o < 256; o <<= 1) {
        int u = (t >= o) ? sd[t - o] : 0;
        __syncthreads();
        sd[t] += u;
        __syncthreads();
    }
    if (i < NBUCK) g_off[i] = sd[t] - v;
    if (t == 255) g_bsum[blockIdx.x] = sd[t];
}
__global__ void k_scanB() {
    if (threadIdx.x == 0) {
        int run = 0;
        for (int b = 0; b < NSCANB; b++) { int s = g_bsum[b]; g_bsum[b] = run; run += s; }
    }
}
__global__ void k_scanC() {
    int i = blockIdx.x * blockDim.x + threadIdx.x;
    if (i < NBUCK) {
        int o = g_off[i] + g_bsum[i >> 8];
        g_off[i] = o;
        g_cur[i] = o;
    }
}
__global__ void k_scatter(const int* __restrict__ src, const int* __restrict__ dst,
                          const int* __restrict__ et) {
    int e = blockIdx.x * blockDim.x + threadIdx.x;
    if (e < NE) {
        int b = dst[e] * NR + et[e];
        int pos = atomicAdd(&g_cur[b], 1);
        g_es[pos] = src[e];
    }
}

// ---------------- CSR aggregation (tf32-rounded output) ----------------
__global__ void k_aggcsr(const float* __restrict__ x0, int sel, int D) {
    int per = D >> 2;
    int npb = 256 / per;
    int local = threadIdx.x / per;
    int j = threadIdx.x - local * per;
    int n = blockIdx.x * npb + local;
    if (n >= NN) return;
    const float* x = (sel == 0) ? x0 : (sel == 1 ? g_h1 : g_h2);
    const float4* x4 = (const float4*)x;
    float4* out4 = (float4*)g_AX;
    size_t obase = (size_t)n * (NR * per);
#pragma unroll
    for (int r = 0; r < NR; r++) {
        int b = n * NR + r;
        int start = g_off[b];
        int cnt = g_cnt[b];
        float4 acc = make_float4(0.f, 0.f, 0.f, 0.f);
        for (int e = 0; e < cnt; e++) {
            int s = g_es[start + e];
            float4 v = x4[(size_t)s * per + j];
            acc.x += v.x; acc.y += v.y; acc.z += v.z; acc.w += v.w;
        }
        float inv = 1.f / fmaxf((float)cnt, 1.f);
        acc.x = rn_tf32f(acc.x * inv);
        acc.y = rn_tf32f(acc.y * inv);
        acc.z = rn_tf32f(acc.z * inv);
        acc.w = rn_tf32f(acc.w * inv);
        out4[obase + r * per + j] = acc;
    }
}

// ---------------- tf32 mma.sync stacked GEMM (pre-rounded operands) + bias + relu ----
// CTA: 128M x 128N, BK=32, 8 warps of 64x32.
// Logical A row n = [ g_AX[n, 0..4D) | H[n, 0..D) ], K = 5D, Kw = 4D. All pre-rounded.
// B = stacked pre-rounded [W|root], row-major [K, F].
#define AS_STRIDE 36
#define BS_STRIDE 132
#define ASZ (128 * AS_STRIDE)
#define BSZ (32 * BS_STRIDE)
#define SM_TOTAL_B ((2 * ASZ + 2 * BSZ) * 4)   // 70656 bytes

__device__ __forceinline__ void cp_async16(unsigned dst, const float* src, int sz) {
    asm volatile("cp.async.ca.shared.global [%0], [%1], 16, %2;"
                 :: "r"(dst), "l"(src), "r"(sz));
}
__device__ __forceinline__ void cp_commit() {
    asm volatile("cp.async.commit_group;" ::: "memory");
}
__device__ __forceinline__ void cp_wait1() {
    asm volatile("cp.async.wait_group 1;" ::: "memory");
}
__device__ __forceinline__ void cp_wait0() {
    asm volatile("cp.async.wait_group 0;" ::: "memory");
}

__global__ __launch_bounds__(256)
void k_gemm_mma(const float* __restrict__ Bmat, const float* __restrict__ bias,
                const float* __restrict__ Hin,
                int M, int D, int F, int osel, int do_round) {
    extern __shared__ float sm[];
    const float* H = Hin;
    float* out = (osel == 1) ? g_h1 : g_h2;
    int K = 5 * D, Kw = 4 * D;

    int t = threadIdx.x, lane = t & 31, wid = t >> 5;
    int row0 = blockIdx.y * 128, col0 = blockIdx.x * 128;
    int m0w = (wid >> 2) * 64, n0w = (wid & 3) * 32;
    int g = lane >> 2, tg = lane & 3;
    int nch = K >> 5;

    float c[4][4][4];
#pragma unroll
    for (int i = 0; i < 4; i++)
#pragma unroll
        for (int j = 0; j < 4; j++)
#pragma unroll
            for (int k = 0; k < 4; k++) c[i][j][k] = 0.f;

    unsigned smb = (unsigned)__cvta_generic_to_shared(sm);

    auto load_chunk = [&](int ch, int buf) {
        unsigned as_b = smb + (buf ? ASZ : 0) * 4;
#pragma unroll
        for (int l = 0; l < 4; l++) {
            int id = t + (l << 8);
            int m = id >> 3, k4 = id & 7;
            int row = row0 + m;
            int krow = (ch << 5) + (k4 << 2);
            const float* src = (krow < Kw) ? (g_AX + (size_t)row * Kw + krow)
                                           : (H + (size_t)row * D + (krow - Kw));
            cp_async16(as_b + (unsigned)(m * AS_STRIDE + k4 * 4) * 4, src, (row < M) ? 16 : 0);
        }
        unsigned bs_b = smb + (2 * ASZ + (buf ? BSZ : 0)) * 4;
#pragma unroll
        for (int l = 0; l < 4; l++) {
            int id = t + (l << 8);
            int k = id >> 5, n4 = id & 31;
            int krow = (ch << 5) + k;
            int col = col0 + (n4 << 2);
            cp_async16(bs_b + (unsigned)(k * BS_STRIDE + n4 * 4) * 4,
                       Bmat + (size_t)krow * F + col, (col < F) ? 16 : 0);
        }
        cp_commit();
    };

    load_chunk(0, 0);

    for (int ch = 0; ch < nch; ch++) {
        if (ch + 1 < nch) load_chunk(ch + 1, (ch + 1) & 1);
        if (ch + 1 < nch) cp_wait1(); else cp_wait0();
        __syncthreads();

        const float* As = sm + ((ch & 1) ? ASZ : 0);
        const float* Bs = sm + 2 * ASZ + ((ch & 1) ? BSZ : 0);

#pragma unroll
        for (int kk = 0; kk < 32; kk += 8) {
            unsigned b[4][2];
#pragma unroll
            for (int nt = 0; nt < 4; nt++) {
                int n = n0w + nt * 8 + g;
                b[nt][0] = __float_as_uint(Bs[(kk + tg) * BS_STRIDE + n]);
                b[nt][1] = __float_as_uint(Bs[(kk + 4 + tg) * BS_STRIDE + n]);
            }
#pragma unroll
            for (int mt = 0; mt < 4; mt++) {
                int m = m0w + mt * 16 + g;
                unsigned a[4];
                a[0] = __float_as_uint(As[m * AS_STRIDE + kk + tg]);
                a[1] = __float_as_uint(As[(m + 8) * AS_STRIDE + kk + tg]);
                a[2] = __float_as_uint(As[m * AS_STRIDE + kk + 4 + tg]);
                a[3] = __float_as_uint(As[(m + 8) * AS_STRIDE + kk + 4 + tg]);
#pragma unroll
                for (int nt = 0; nt < 4; nt++)
                    asm volatile(
                        "mma.sync.aligned.m16n8k8.row.col.f32.tf32.tf32.f32 "
                        "{%0,%1,%2,%3},{%4,%5,%6,%7},{%8,%9},{%0,%1,%2,%3};"
                        : "+f"(c[mt][nt][0]), "+f"(c[mt][nt][1]),
                          "+f"(c[mt][nt][2]), "+f"(c[mt][nt][3])
                        : "r"(a[0]), "r"(a[1]), "r"(a[2]), "r"(a[3]),
                          "r"(b[nt][0]), "r"(b[nt][1]));
            }
        }
        __syncthreads();
    }

    // ---- epilogue: bias + relu (+ tf32 rounding for h feeding the next layer) ----
#pragma unroll
    for (int mt = 0; mt < 4; mt++) {
        int r0 = row0 + m0w + mt * 16 + g;
#pragma unroll
        for (int nt = 0; nt < 4; nt++) {
            int cb = col0 + n0w + nt * 8 + tg * 2;
            if (cb < F) {
                float b0 = bias[cb], b1 = bias[cb + 1];
                float v0 = fmaxf(c[mt][nt][0] + b0, 0.f);
                float v1 = fmaxf(c[mt][nt][1] + b1, 0.f);
                float v2 = fmaxf(c[mt][nt][2] + b0, 0.f);
                float v3 = fmaxf(c[mt][nt][3] + b1, 0.f);
                if (do_round) {
                    v0 = rn_tf32f(v0); v1 = rn_tf32f(v1);
                    v2 = rn_tf32f(v2); v3 = rn_tf32f(v3);
                }
                if (r0 < M) *(float2*)(out + (size_t)r0 * F + cb) = make_float2(v0, v1);
                if (r0 + 8 < M) *(float2*)(out + (size_t)(r0 + 8) * F + cb) = make_float2(v2, v3);
            }
        }
    }
}

// ---------------- pooling ----------------
__global__ void k_zero_pool() {
    int i = blockIdx.x * blockDim.x + threadIdx.x;
    if (i < NG * F3) g_pool[i] = 0.f;
    if (i < NG) g_pcnt[i] = 0.f;
}
__global__ void k_pcnt(const int* __restrict__ batch) {
    int i = blockIdx.x * blockDim.x + threadIdx.x;
    if (i < NN) atomicAdd(&g_pcnt[batch[i]], 1.f);
}
__global__ void k_pool(const int* __restrict__ batch) {
    const int per = F3 / 4;
    long total = (long)NN * per;
    long i = (long)blockIdx.x * blockDim.x + threadIdx.x;
    if (i >= total) return;
    int n = (int)(i / per);
    int j = (int)(i % per);
    int b = batch[n];
    float4 v = ((const float4*)g_h1)[(long)n * per + j];
    float* base = g_pool + (long)b * F3 + j * 4;
    atomicAdd(base + 0, v.x);
    atomicAdd(base + 1, v.y);
    atomicAdd(base + 2, v.z);
    atomicAdd(base + 3, v.w);
}

// ---------------- final MLP ----------------
__global__ void k_mlp(const float* __restrict__ fw1, const float* __restrict__ fb1,
                      const float* __restrict__ fw2, const float* __restrict__ fb2,
                      float* __restrict__ out) {
    __shared__ float gbuf[F3];
    __shared__ float abuf[64];
    int g = blockIdx.x;
    int t = threadIdx.x;
    float invc = 1.f / fmaxf(g_pcnt[g], 1.f);
    for (int i = t; i < F3; i += blockDim.x)
        gbuf[i] = g_pool[(long)g * F3 + i] * invc;
    __syncthreads();
    if (t < 64) {
        float s = fb1[t];
        for (int k = 0; k < F3; k++) s += gbuf[k] * fw1[k * 64 + t];
        abuf[t] = fmaxf(s, 0.f);
    }
    __syncthreads();
    if (t == 0) {
        float o = fb2[0];
#pragma unroll
        for (int j = 0; j < 64; j++) o += abuf[j] * fw2[j];
        out[g] = o;
    }
}

// ---------------- launch ----------------
extern "C" void kernel_launch(void* const* d_in, const int* in_sizes, int n_in,
                              void* d_out, int out_size) {
    const float* x    = (const float*)d_in[0];
    const int*   ei   = (const int*)d_in[1];
    const int*   et   = (const int*)d_in[2];
    const int*   batch= (const int*)d_in[3];
    const float* W1   = (const float*)d_in[4];
    const float* r1   = (const float*)d_in[5];
    const float* b1   = (const float*)d_in[6];
    const float* W2   = (const float*)d_in[7];
    const float* r2   = (const float*)d_in[8];
    const float* b2   = (const float*)d_in[9];
    const float* W3   = (const float*)d_in[10];
    const float* r3   = (const float*)d_in[11];
    const float* b3   = (const float*)d_in[12];
    const float* fw1  = (const float*)d_in[13];
    const float* fb1  = (const float*)d_in[14];
    const float* fw2  = (const float*)d_in[15];
    const float* fb2  = (const float*)d_in[16];
    float* out = (float*)d_out;

    const int* srcI = ei;
    const int* dstI = ei + NE;

    cudaFuncSetAttribute(k_gemm_mma, cudaFuncAttributeMaxDynamicSharedMemorySize, SM_TOTAL_B);

    // device pointers to __device__ scratch for kernel args
    float *pB1, *pB2, *pB3, *pXr;
    cudaGetSymbolAddress((void**)&pB1, g_B1);
    cudaGetSymbolAddress((void**)&pB2, g_B2);
    cudaGetSymbolAddress((void**)&pB3, g_B3);
    cudaGetSymbolAddress((void**)&pXr, g_xr);

    // ---- weight / input pre-rounding (tf32) ----
    {
        long n1 = (long)320 * 1024;
        k_wconv<<<(int)((n1 / 4 + 255) / 256), 256>>>(W1, r1, pB1, (long)256 * 1024, n1);
        long n2 = (long)5120 * 1024;
        k_wconv<<<(int)((n2 / 4 + 255) / 256), 256>>>(W2, r2, pB2, (long)4096 * 1024, n2);
        long n3 = (long)5120 * 712;
        k_wconv<<<(int)((n3 / 4 + 255) / 256), 256>>>(W3, r3, pB3, (long)4096 * 712, n3);
        k_xconv<<<(NN * 64 / 4 + 255) / 256, 256>>>(x);
    }

    // ---- CSR build ----
    k_zero_cnt<<<(NBUCK + 255) / 256, 256>>>();
    k_count<<<(NE + 255) / 256, 256>>>(dstI, et);
    k_scanA<<<NSCANB, 256>>>();
    k_scanB<<<1, 32>>>();
    k_scanC<<<NSCANB, 256>>>();
    k_scatter<<<(NE + 255) / 256, 256>>>(srcI, dstI, et);

    // ---- layer 1: D=64 -> F=1024 ----
    {
        const int D = 64, F = 1024;
        int per = D / 4, npb = 256 / per;
        k_aggcsr<<<(NN + npb - 1) / npb, 256>>>(pXr, 0, D);
        dim3 grid((F + 127) / 128, (NN + 127) / 128);
        k_gemm_mma<<<grid, 256, SM_TOTAL_B>>>(pB1, b1, pXr, NN, D, F, 1, 1);
    }
    // ---- layer 2: D=1024 -> F=1024 ----
    {
        const int D = 1024, F = 1024;
        float* pH1; cudaGetSymbolAddress((void**)&pH1, g_h1);
        k_aggcsr<<<NN, 256>>>(nullptr, 1, D);
        dim3 grid((F + 127) / 128, (NN + 127) / 128);
        k_gemm_mma<<<grid, 256, SM_TOTAL_B>>>(pB2, b2, pH1, NN, D, F, 2, 1);
    }
    // ---- layer 3: D=1024 -> F=712 ----
    {
        const int D = 1024, F = F3;
        float* pH2; cudaGetSymbolAddress((void**)&pH2, g_h2);
        k_aggcsr<<<NN, 256>>>(nullptr, 2, D);
        dim3 grid((F + 127) / 128, (NN + 127) / 128);
        k_gemm_mma<<<grid, 256, SM_TOTAL_B>>>(pB3, b3, pH2, NN, D, F, 1, 0);
    }

    // ---- global mean pool + MLP ----
    k_zero_pool<<<(NG * F3 + 255) / 256, 256>>>();
    k_pcnt<<<(NN + 255) / 256, 256>>>(batch);
    {
        long tp = (long)NN * (F3 / 4);
        k_pool<<<(int)((tp + 255) / 256), 256>>>(batch);
    }
    k_mlp<<<NG, 128>>>(fw1, fb1, fw2, fb2, out);
}